// round 9
// baseline (speedup 1.0000x reference)
#include <cuda_runtime.h>

// ---------------- problem constants ----------------
#define T_STEPS 131   // 128 story + 1 query + 2 empty
#define BSZ     64
#define EMB     128
#define HID     256
#define VOCAB   32000
#define MSTL    128
#define MSEL    24
#define QL      16

// ---------------- scratch ----------------
// d_X: [t(<=128)][bt8][e128][b8]  (per-CTA tile contiguous 4KB)
__device__ __align__(16) float d_X[129 * 8 * EMB * 8];
// d_H: h double buffer [buf2][bt8][k256][b8] (per-warp row = 32B)
__device__ __align__(16) float d_H[2 * 8 * HID * 8];
// flag per (t, bt, producer ht, producer warp)
#define NFLAGS (T_STEPS * 8 * 16 * 16)
__device__ unsigned d_flag[NFLAGS];

// ---------------- helpers ----------------
typedef unsigned long long u64;

__device__ __forceinline__ u64 pack2(float x, float y) {
    u64 r; asm("mov.b64 %0, {%1, %2};" : "=l"(r) : "f"(x), "f"(y)); return r;
}
__device__ __forceinline__ void ffma2(u64& acc, u64 a, u64 b) {
    asm("fma.rn.f32x2 %0, %1, %2, %0;" : "+l"(acc) : "l"(a), "l"(b));
}
__device__ __forceinline__ u64 addx2(u64 a, u64 b) {
    u64 r; asm("add.rn.f32x2 %0, %1, %2;" : "=l"(r) : "l"(a), "l"(b)); return r;
}
__device__ __forceinline__ void lds_2x64(u64& p0, u64& p1, unsigned addr) {
    asm volatile("ld.shared.v2.u64 {%0, %1}, [%2];" : "=l"(p0), "=l"(p1) : "r"(addr));
}
__device__ __forceinline__ void unpack2(u64 p, float& x, float& y) {
    asm("mov.b64 {%0, %1}, %2;" : "=f"(x), "=f"(y) : "l"(p));
}
__device__ __forceinline__ void cp_async16(unsigned smem, const void* gptr) {
    asm volatile("cp.async.cg.shared.global [%0], [%1], 16;" :: "r"(smem), "l"(gptr));
}
__device__ __forceinline__ void cp_commit() { asm volatile("cp.async.commit_group;"); }
__device__ __forceinline__ void cp_wait0()  { asm volatile("cp.async.wait_group 0;"); }

__device__ __forceinline__ unsigned ld_acq(const unsigned* p) {
    unsigned v;
    asm volatile("ld.acquire.gpu.global.b32 %0, [%1];" : "=r"(v) : "l"(p));
    return v;
}
__device__ __forceinline__ void st_rel(unsigned* p, unsigned v) {
    asm volatile("st.release.gpu.global.b32 [%0], %1;" :: "l"(p), "r"(v));
}

__device__ __forceinline__ float sigf(float x) {
    return 1.0f / (1.0f + __expf(-x));
}
__device__ __forceinline__ float tanh_f(float x) {
    float a = fabsf(x);
    float e = __expf(-2.0f * a);
    float r = (1.0f - e) / (1.0f + e);
    return copysignf(r, x);
}

// ============================================================================
// Kernel 0: clear flags (graph replays must start from zero)
// ============================================================================
__global__ void clear_flags_kernel() {
    int i = blockIdx.x * 256 + threadIdx.x;        // 16B per thread
    ((uint4*)d_flag)[i] = make_uint4(0, 0, 0, 0);
}

// ============================================================================
// Kernel 1: embedding gather + position encoding -> d_X [t][bt8][e][8b]
// ============================================================================
__global__ void encode_kernel(const int* __restrict__ story,
                              const int* __restrict__ query,
                              const float* __restrict__ E) {
    int wid  = blockIdx.x * 8 + (threadIdx.x >> 5);
    int lane = threadIdx.x & 31;
    int b = wid / T_STEPS;
    int t = wid % T_STEPS;
    if (t > MSTL) return;
    int e0 = lane * 4;

    const float invE = 1.0f / (float)EMB;
    float k0 = (e0 + 1) * invE;
    float k1 = (e0 + 2) * invE;
    float k2 = (e0 + 3) * invE;
    float k3 = (e0 + 4) * invE;

    float4 acc = make_float4(0.f, 0.f, 0.f, 0.f);

    if (t < MSTL) {
        const int* toks = story + (b * MSTL + t) * MSEL;
#pragma unroll
        for (int s = 0; s < MSEL; ++s) {
            int tok = toks[s];
            float j = (s + 1) * (1.0f / 32.0f);
            float A = 1.0f - j, Bc = 1.0f - 2.0f * j;
            float4 ev = *(const float4*)(E + tok * EMB + e0);
            acc.x += ev.x * (A - k0 * Bc);
            acc.y += ev.y * (A - k1 * Bc);
            acc.z += ev.z * (A - k2 * Bc);
            acc.w += ev.w * (A - k3 * Bc);
        }
    } else {
        const int* toks = query + b * QL;
#pragma unroll
        for (int s = 0; s < QL; ++s) {
            int tok = toks[s];
            float j = (s + 1) * (1.0f / 32.0f);
            float A = 1.0f - j, Bc = 1.0f - 2.0f * j;
            float4 ev = *(const float4*)(E + tok * EMB + e0);
            acc.x += ev.x * (A - k0 * Bc);
            acc.y += ev.y * (A - k1 * Bc);
            acc.z += ev.z * (A - k2 * Bc);
            acc.w += ev.w * (A - k3 * Bc);
        }
    }
    float* dst = d_X + ((t * 8 + (b >> 3)) * EMB) * 8 + (b & 7);
    dst[(e0 + 0) * 8] = acc.x;
    dst[(e0 + 1) * 8] = acc.y;
    dst[(e0 + 2) * 8] = acc.z;
    dst[(e0 + 3) * 8] = acc.w;
}

// ============================================================================
// Kernel 2: persistent LSTM, warp-owns-unit, per-warp flag exchange
//   128 CTAs = 16 ht x 8 bt; 512 threads = 16 warps.
//   Warp w -> hidden unit u = ht*16 + w. Lane = g*8 + kc (gate, k-chunk).
//   Padded SMEM blocks: 16 rows x 8b = 512B data + 16B pad = 528B stride
//   (8 kc-blocks start on 8 disjoint 4-bank groups -> conflict-free LDS.128).
// ============================================================================
#define RGRID 128
#define RTHREADS 512
#define BLK 132              // block stride in floats
#define XBUF_F (8 * BLK)     // floats per x buffer
#define HBUF_F (16 * BLK)    // floats per h buffer

__global__ void __launch_bounds__(RTHREADS, 1)
lstm_kernel(const float* __restrict__ W_ih, const float* __restrict__ W_hh,
            const float* __restrict__ b_ih, const float* __restrict__ b_hh) {
    __shared__ __align__(16) float xsh[2 * XBUF_F];
    __shared__ __align__(16) float hsh[2 * HBUF_F];

    const int tid  = threadIdx.x;
    const int bt   = blockIdx.x & 7;
    const int ht   = blockIdx.x >> 3;
    const int w    = tid >> 5;            // warp id = local unit
    const int lane = tid & 31;
    const int g    = lane >> 3;           // gate 0..3 (i,f,g,o)
    const int kc   = lane & 7;            // k-chunk 0..7
    const int u    = ht * 16 + w;         // global hidden unit
    const int grow = g * 256 + u;         // gate row

    // ---- register weights ----
    float4 wih[4];   // W_ih[grow][kc*16 .. +16)
    float4 whh[8];   // W_hh[grow][kc*16..+16) and [128+kc*16..+16)
    {
        const float4* p = (const float4*)(W_ih + grow * EMB + kc * 16);
#pragma unroll
        for (int q = 0; q < 4; ++q) wih[q] = p[q];
        const float4* pa = (const float4*)(W_hh + grow * HID + kc * 16);
#pragma unroll
        for (int q = 0; q < 4; ++q) whh[q] = pa[q];
        const float4* pb = (const float4*)(W_hh + grow * HID + 128 + kc * 16);
#pragma unroll
        for (int q = 0; q < 4; ++q) whh[4 + q] = pb[q];
    }
    float bi = b_ih[0 * 256 + u] + b_hh[0 * 256 + u];
    float bf = b_ih[1 * 256 + u] + b_hh[1 * 256 + u];
    float bg = b_ih[2 * 256 + u] + b_hh[2 * 256 + u];
    float bo = b_ih[3 * 256 + u] + b_hh[3 * 256 + u];

    const unsigned xsb = (unsigned)__cvta_generic_to_shared(xsh);
    const unsigned hsb = (unsigned)__cvta_generic_to_shared(hsh);

    // ---- prefetch x(0) ----
    if (lane < 16) {
        unsigned dst = xsb + ((w >> 1) * BLK + ((w & 1) * 16 + lane) * 4) * 4;
        const float* src = d_X + (0 * 8 + bt) * (EMB * 8)
                         + (w >> 1) * 128 + ((w & 1) * 16 + lane) * 4;
        cp_async16(dst, src);
    }
    cp_commit();
    cp_wait0();
    __syncthreads();

    float c = 0.0f;   // cell state for batch lane&7 (redundant x4 across g)

    for (int t = 0; t < T_STEPS; ++t) {
        u64 a0 = 0, a1 = 0, a2 = 0, a3 = 0;

        // ---- (a) x-part GEMM on xsh[t&1] (FULL 8-batch rows) ----
        if (t <= MSTL) {
            const unsigned xb = xsb + (t & 1) * (XBUF_F * 4) + kc * (BLK * 4);
#pragma unroll
            for (int q = 0; q < 4; ++q) {
                float4 w4 = wih[q];
#pragma unroll
                for (int cc = 0; cc < 4; ++cc) {
                    float wv = (cc == 0) ? w4.x : (cc == 1) ? w4.y : (cc == 2) ? w4.z : w4.w;
                    u64 wd = pack2(wv, wv);
                    u64 p0, p1, p2, p3;
                    unsigned ad = xb + (q * 4 + cc) * 32;
                    lds_2x64(p0, p1, ad);         // batches 0-3
                    lds_2x64(p2, p3, ad + 16);    // batches 4-7
                    ffma2(a0, wd, p0); ffma2(a1, wd, p1);
                    ffma2(a2, wd, p2); ffma2(a3, wd, p3);
                }
            }
        }

        // ---- (b) poll producer flags + (c) stage h / prefetch x ----
        if (t > 0 && w != ht) {
            if (lane < 16) {
                const unsigned* fp =
                    &d_flag[(((t - 1) * 8 + bt) * 16 + w) * 16 + lane];
                while (ld_acq(fp) == 0) { }
            }
            __syncwarp();
            unsigned dst = hsb + (((t - 1) & 1) * HBUF_F + w * BLK) * 4 + lane * 16;
            const float* src = d_H + (((t - 1) & 1) * 8 + bt) * (HID * 8)
                             + w * 128 + lane * 4;
            cp_async16(dst, src);
        }
        if (t < MSTL && lane < 16) {
            unsigned dst = xsb + (((t + 1) & 1) * XBUF_F
                         + (w >> 1) * BLK + ((w & 1) * 16 + lane) * 4) * 4;
            const float* src = d_X + ((t + 1) * 8 + bt) * (EMB * 8)
                             + (w >> 1) * 128 + ((w & 1) * 16 + lane) * 4;
            cp_async16(dst, src);
        }
        cp_commit();
        cp_wait0();
        __syncthreads();   // (d) single CTA barrier per step

        // ---- (e) h-part GEMM on hsh[(t-1)&1] (FULL 8-batch rows) ----
        if (t > 0) {
            const unsigned hbA = hsb + (((t - 1) & 1) * HBUF_F + kc * BLK) * 4;
            const unsigned hbB = hsb + (((t - 1) & 1) * HBUF_F + (8 + kc) * BLK) * 4;
#pragma unroll
            for (int q = 0; q < 4; ++q) {
                float4 w4 = whh[q];
#pragma unroll
                for (int cc = 0; cc < 4; ++cc) {
                    float wv = (cc == 0) ? w4.x : (cc == 1) ? w4.y : (cc == 2) ? w4.z : w4.w;
                    u64 wd = pack2(wv, wv);
                    u64 p0, p1, p2, p3;
                    unsigned ad = hbA + (q * 4 + cc) * 32;
                    lds_2x64(p0, p1, ad);
                    lds_2x64(p2, p3, ad + 16);
                    ffma2(a0, wd, p0); ffma2(a1, wd, p1);
                    ffma2(a2, wd, p2); ffma2(a3, wd, p3);
                }
            }
#pragma unroll
            for (int q = 0; q < 4; ++q) {
                float4 w4 = whh[4 + q];
#pragma unroll
                for (int cc = 0; cc < 4; ++cc) {
                    float wv = (cc == 0) ? w4.x : (cc == 1) ? w4.y : (cc == 2) ? w4.z : w4.w;
                    u64 wd = pack2(wv, wv);
                    u64 p0, p1, p2, p3;
                    unsigned ad = hbB + (q * 4 + cc) * 32;
                    lds_2x64(p0, p1, ad);
                    lds_2x64(p2, p3, ad + 16);
                    ffma2(a0, wd, p0); ffma2(a1, wd, p1);
                    ffma2(a2, wd, p2); ffma2(a3, wd, p3);
                }
            }
        }

        // ---- (f) kc-reduction: 3 butterfly rounds on lane bits 0..2 ----
#pragma unroll
        for (int m = 1; m <= 4; m <<= 1) {
            a0 = addx2(a0, __shfl_xor_sync(0xffffffffu, a0, m));
            a1 = addx2(a1, __shfl_xor_sync(0xffffffffu, a1, m));
            a2 = addx2(a2, __shfl_xor_sync(0xffffffffu, a2, m));
            a3 = addx2(a3, __shfl_xor_sync(0xffffffffu, a3, m));
        }

        // ---- (g) select own batch + gather 4 gates ----
        float f0, f1, f2, f3, f4, f5, f6, f7;
        unpack2(a0, f0, f1); unpack2(a1, f2, f3);
        unpack2(a2, f4, f5); unpack2(a3, f6, f7);
        const int b = lane & 7;
        float m0 = (b & 1) ? f1 : f0, m1 = (b & 1) ? f3 : f2;
        float m2 = (b & 1) ? f5 : f4, m3 = (b & 1) ? f7 : f6;
        float n0 = (b & 2) ? m1 : m0, n1 = (b & 2) ? m3 : m2;
        float mine = (b & 4) ? n1 : n0;
        float vi = __shfl_sync(0xffffffffu, mine, b);
        float vf = __shfl_sync(0xffffffffu, mine, 8 + b);
        float vg = __shfl_sync(0xffffffffu, mine, 16 + b);
        float vo = __shfl_sync(0xffffffffu, mine, 24 + b);

        // ---- (h) pointwise ----
        float ig = sigf(vi + bi);
        float fg = sigf(vf + bf);
        float gv = tanh_f(vg + bg);
        float og = sigf(vo + bo);
        c = fg * c + ig * gv;
        float h = og * tanh_f(c);

        // ---- (i,j) publish h: local STS + global STG ----
        if (lane < 8) {
            hsh[(t & 1) * HBUF_F + ht * BLK + w * 8 + b] = h;
            __stcg(&d_H[((t & 1) * 8 + bt) * (HID * 8) + u * 8 + b], h);
        }
        // ---- (k) per-warp flag release (no end-of-step CTA barrier) ----
        __syncwarp();
        if (t < T_STEPS - 1 && lane == 0)
            st_rel(&d_flag[((t * 8 + bt) * 16 + ht) * 16 + w], 1u);
    }
}

// ============================================================================
// Kernel 3: logits = h @ lin_W.T + lin_b, grid (125, 2): batch halves
// ============================================================================
__global__ void __launch_bounds__(256, 1)
out_kernel(const float* __restrict__ lin_W, const float* __restrict__ lin_b,
           float* __restrict__ out) {
    __shared__ __align__(16) float hsh[HID * 32];   // [k256][32b] = 32KB
    const int tid  = threadIdx.x;
    const int half = blockIdx.y;

    for (int idx = tid; idx < HID * 32; idx += 256) {
        int k = idx >> 5, bl = idx & 31;
        int gb = half * 32 + bl;
        hsh[idx] = d_H[(gb >> 3) * (HID * 8) + k * 8 + (gb & 7)];
    }
    __syncthreads();

    const int v = blockIdx.x * 256 + tid;
    const unsigned hb = (unsigned)__cvta_generic_to_shared(hsh);

    float bbv = lin_b[v];
    u64 acc[16];
    u64 bp = pack2(bbv, bbv);
#pragma unroll
    for (int j = 0; j < 16; ++j) acc[j] = bp;

    const float4* wp = (const float4*)(lin_W + v * HID);
#pragma unroll 4
    for (int kk = 0; kk < HID / 4; ++kk) {
        float4 w4 = wp[kk];
#pragma unroll
        for (int cc = 0; cc < 4; ++cc) {
            float wv = (cc == 0) ? w4.x : (cc == 1) ? w4.y : (cc == 2) ? w4.z : w4.w;
            u64 wd = pack2(wv, wv);
            unsigned base = hb + ((kk * 4 + cc) * 32) * 4;
#pragma unroll
            for (int p = 0; p < 4; ++p) {
                u64 q0, q1;
                lds_2x64(q0, q1, base + p * 32);
                ffma2(acc[p * 4 + 0], wd, q0);
                ffma2(acc[p * 4 + 1], wd, q1);
                u64 q2, q3;
                lds_2x64(q2, q3, base + p * 32 + 16);
                ffma2(acc[p * 4 + 2], wd, q2);
                ffma2(acc[p * 4 + 3], wd, q3);
            }
        }
    }
#pragma unroll
    for (int p = 0; p < 4; ++p)
#pragma unroll
        for (int i = 0; i < 4; ++i) {
            float x0, x1;
            unpack2(acc[p * 4 + i], x0, x1);
            int gb = half * 32 + p * 8 + i * 2;
            out[gb * VOCAB + v]       = x0;
            out[(gb + 1) * VOCAB + v] = x1;
        }
}

// ============================================================================
// launch
// ============================================================================
extern "C" void kernel_launch(void* const* d_in, const int* in_sizes, int n_in,
                              void* d_out, int out_size) {
    const int*   story  = (const int*)d_in[0];
    const int*   query  = (const int*)d_in[1];
    const float* E      = (const float*)d_in[2];
    const float* W_ih   = (const float*)d_in[3];
    const float* W_hh   = (const float*)d_in[4];
    const float* b_ih   = (const float*)d_in[5];
    const float* b_hh   = (const float*)d_in[6];
    const float* lin_W  = (const float*)d_in[7];
    const float* lin_b  = (const float*)d_in[8];
    float*       out    = (float*)d_out;

    clear_flags_kernel<<<NFLAGS / (256 * 4), 256>>>();
    encode_kernel<<<(T_STEPS * BSZ) / 8, 256>>>(story, query, E);
    lstm_kernel<<<RGRID, RTHREADS>>>(W_ih, W_hh, b_ih, b_hh);
    dim3 og(VOCAB / 256, 2);
    out_kernel<<<og, 256>>>(lin_W, lin_b, out);
}

// round 10
// speedup vs baseline: 1.3894x; 1.3894x over previous
#include <cuda_runtime.h>

// ---------------- problem constants ----------------
#define T_STEPS 131   // 128 story + 1 query + 2 empty
#define BSZ     64
#define EMB     128
#define HID     256
#define VOCAB   32000
#define MSTL    128
#define MSEL    24
#define QL      16

// ---------------- scratch ----------------
// d_X: [t(<=128)][bt8][e128][b8]  (per-CTA tile contiguous 4KB)
__device__ __align__(16) float d_X[129 * 8 * EMB * 8];
// d_H: h double buffer [buf2][bt8][k256][b8] (per-producer block = 512B)
__device__ __align__(16) float d_H[2 * 8 * HID * 8];
// one flag per (t, bt, producer ht); cleared before each run
#define NFLAGS (T_STEPS * 8 * 16)
__device__ unsigned d_flag[NFLAGS];

// ---------------- helpers ----------------
typedef unsigned long long u64;

__device__ __forceinline__ u64 pack2(float x, float y) {
    u64 r; asm("mov.b64 %0, {%1, %2};" : "=l"(r) : "f"(x), "f"(y)); return r;
}
__device__ __forceinline__ void ffma2(u64& acc, u64 a, u64 b) {
    asm("fma.rn.f32x2 %0, %1, %2, %0;" : "+l"(acc) : "l"(a), "l"(b));
}
__device__ __forceinline__ void lds_2x64(u64& p0, u64& p1, unsigned addr) {
    asm volatile("ld.shared.v2.u64 {%0, %1}, [%2];" : "=l"(p0), "=l"(p1) : "r"(addr));
}
__device__ __forceinline__ void sts_2x64(unsigned addr, u64 p0, u64 p1) {
    asm volatile("st.shared.v2.u64 [%0], {%1, %2};" :: "r"(addr), "l"(p0), "l"(p1));
}
__device__ __forceinline__ void unpack2(u64 p, float& x, float& y) {
    asm("mov.b64 {%0, %1}, %2;" : "=f"(x), "=f"(y) : "l"(p));
}
__device__ __forceinline__ void cp_async16(unsigned smem, const void* gptr) {
    asm volatile("cp.async.cg.shared.global [%0], [%1], 16;" :: "r"(smem), "l"(gptr));
}
__device__ __forceinline__ void cp_commit() { asm volatile("cp.async.commit_group;"); }
__device__ __forceinline__ void cp_wait0()  { asm volatile("cp.async.wait_group 0;"); }

__device__ __forceinline__ unsigned ld_acq(const unsigned* p) {
    unsigned v;
    asm volatile("ld.acquire.gpu.global.b32 %0, [%1];" : "=r"(v) : "l"(p));
    return v;
}
__device__ __forceinline__ void st_rel(unsigned* p, unsigned v) {
    asm volatile("st.release.gpu.global.b32 [%0], %1;" :: "l"(p), "r"(v));
}

__device__ __forceinline__ float sigf(float x) {
    return 1.0f / (1.0f + __expf(-x));
}
__device__ __forceinline__ float tanh_f(float x) {
    float a = fabsf(x);
    float e = __expf(-2.0f * a);
    float r = (1.0f - e) / (1.0f + e);
    return copysignf(r, x);
}

// ============================================================================
// Kernel 0: clear flags (graph replays must start from zero)
// ============================================================================
__global__ void clear_flags_kernel() {
    int i = blockIdx.x * 256 + threadIdx.x;
    if (i < NFLAGS) d_flag[i] = 0;
}

// ============================================================================
// Kernel 1: embedding gather + position encoding -> d_X [t][bt8][e][8b]
// ============================================================================
__global__ void encode_kernel(const int* __restrict__ story,
                              const int* __restrict__ query,
                              const float* __restrict__ E) {
    int wid  = blockIdx.x * 8 + (threadIdx.x >> 5);
    int lane = threadIdx.x & 31;
    int b = wid / T_STEPS;
    int t = wid % T_STEPS;
    if (t > MSTL) return;
    int e0 = lane * 4;

    const float invE = 1.0f / (float)EMB;
    float k0 = (e0 + 1) * invE;
    float k1 = (e0 + 2) * invE;
    float k2 = (e0 + 3) * invE;
    float k3 = (e0 + 4) * invE;

    float4 acc = make_float4(0.f, 0.f, 0.f, 0.f);

    if (t < MSTL) {
        const int* toks = story + (b * MSTL + t) * MSEL;
#pragma unroll
        for (int s = 0; s < MSEL; ++s) {
            int tok = toks[s];
            float j = (s + 1) * (1.0f / 32.0f);
            float A = 1.0f - j, Bc = 1.0f - 2.0f * j;
            float4 ev = *(const float4*)(E + tok * EMB + e0);
            acc.x += ev.x * (A - k0 * Bc);
            acc.y += ev.y * (A - k1 * Bc);
            acc.z += ev.z * (A - k2 * Bc);
            acc.w += ev.w * (A - k3 * Bc);
        }
    } else {
        const int* toks = query + b * QL;
#pragma unroll
        for (int s = 0; s < QL; ++s) {
            int tok = toks[s];
            float j = (s + 1) * (1.0f / 32.0f);
            float A = 1.0f - j, Bc = 1.0f - 2.0f * j;
            float4 ev = *(const float4*)(E + tok * EMB + e0);
            acc.x += ev.x * (A - k0 * Bc);
            acc.y += ev.y * (A - k1 * Bc);
            acc.z += ev.z * (A - k2 * Bc);
            acc.w += ev.w * (A - k3 * Bc);
        }
    }
    float* dst = d_X + ((t * 8 + (b >> 3)) * EMB) * 8 + (b & 7);
    dst[(e0 + 0) * 8] = acc.x;
    dst[(e0 + 1) * 8] = acc.y;
    dst[(e0 + 2) * 8] = acc.z;
    dst[(e0 + 3) * 8] = acc.w;
}

// ============================================================================
// Kernel 2: persistent LSTM recurrence, flag-based L2 exchange (R6 design)
//   128 CTAs = 16 ht x 8 bt, 512 threads: kc=tid>>6 (k-chunk 0..7), r=tid&63.
//   Operand SMEM loads are warp-broadcast (lanes of a warp share kc? no:
//   lanes of a warp span r -> same kc rows -> same addresses -> N=1).
// ============================================================================
#define RGRID 128
#define RTHREADS 512

__global__ void __launch_bounds__(RTHREADS, 1)
lstm_kernel(const float* __restrict__ W_ih, const float* __restrict__ W_hh,
            const float* __restrict__ b_ih, const float* __restrict__ b_hh) {
    __shared__ __align__(16) float xsh[2][EMB * 8];   // 2 x 4KB, [e][8b]
    __shared__ __align__(16) float hsh[HID * 8];      // 8KB, [k][8b]
    __shared__ __align__(16) float psh[512 * 8];      // 16KB partials
    __shared__ float bsh[64];

    const int tid = threadIdx.x;
    const int bt  = blockIdx.x & 7;
    const int ht  = blockIdx.x >> 3;
    const int kc  = tid >> 6;          // 0..7
    const int r   = tid & 63;          // g*16 + jj
    const int grow = (r >> 4) * 256 + ht * 16 + (r & 15);

    // ---- register-resident weight slices ----
    float4 wih[4];    // W_ih[grow][kc*16 .. +16)
    float4 whh[8];    // W_hh[grow][kc*32 .. +32)
    {
        const float4* p = (const float4*)(W_ih + grow * EMB + kc * 16);
#pragma unroll
        for (int q = 0; q < 4; ++q) wih[q] = p[q];
        const float4* ph = (const float4*)(W_hh + grow * HID + kc * 32);
#pragma unroll
        for (int q = 0; q < 8; ++q) whh[q] = ph[q];
    }
    if (tid < 64) {
        int gr = (tid >> 4) * 256 + ht * 16 + (tid & 15);
        bsh[tid] = b_ih[gr] + b_hh[gr];
    }

    const unsigned xs0  = (unsigned)__cvta_generic_to_shared(&xsh[0][0]);
    const unsigned hsb  = (unsigned)__cvta_generic_to_shared(hsh);
    const unsigned hbase = hsb + kc * 1024;
    const unsigned pbase = (unsigned)__cvta_generic_to_shared(psh) + tid * 32;

    const int w    = tid >> 5;   // warp id 0..15 (one producer each)
    const int lane = tid & 31;

    // prefetch x(0)
    if (tid < 256) cp_async16(xs0 + tid * 16, d_X + bt * (EMB * 8) + tid * 4);
    cp_commit();

    float c = 0.0f;
    __syncthreads();   // bsh ready

    for (int t = 0; t < T_STEPS; ++t) {
        u64 a0 = 0, a1 = 0, a2 = 0, a3 = 0;

        if (t <= MSTL) {
            cp_wait0();
            __syncthreads();                        // x(t) visible CTA-wide
            if (t < MSTL) {
                if (tid < 256)
                    cp_async16(xs0 + (((t + 1) & 1) ? 4096 : 0) + tid * 16,
                               d_X + (((t + 1) * 8 + bt) * EMB) * 8 + tid * 4);
                cp_commit();
            }
            // ---- x-part GEMM (latency filler before the flag wait) ----
            const unsigned xb = xs0 + ((t & 1) ? 4096 : 0) + kc * 512;
#pragma unroll
            for (int q = 0; q < 4; ++q) {
                float4 w4 = wih[q];
#pragma unroll
                for (int cc = 0; cc < 4; ++cc) {
                    float wv = (cc == 0) ? w4.x : (cc == 1) ? w4.y : (cc == 2) ? w4.z : w4.w;
                    u64 wd = pack2(wv, wv);
                    u64 p0, p1, p2, p3;
                    unsigned ad = xb + (q * 4 + cc) * 32;
                    lds_2x64(p0, p1, ad);
                    lds_2x64(p2, p3, ad + 16);
                    ffma2(a0, wd, p0); ffma2(a1, wd, p1);
                    ffma2(a2, wd, p2); ffma2(a3, wd, p3);
                }
            }
        }

        if (t > 0) {
            // ---- fine-grained exchange: warp w waits on producer w, then
            //      streams its 512B h-block ----
            const unsigned* fp = &d_flag[((t - 1) * 8 + bt) * 16 + w];
            while (ld_acq(fp) == 0) { }
            const float* src = d_H + (((t - 1) & 1) * 8 + bt) * (HID * 8)
                               + w * 128 + lane * 4;
            cp_async16(hsb + w * 512 + lane * 16, src);
            cp_commit();
            cp_wait0();
            __syncthreads();                        // whole h(t-1) tile visible

            // ---- h-part GEMM ----
#pragma unroll
            for (int q = 0; q < 8; ++q) {
                float4 w4 = whh[q];
#pragma unroll
                for (int cc = 0; cc < 4; ++cc) {
                    float wv = (cc == 0) ? w4.x : (cc == 1) ? w4.y : (cc == 2) ? w4.z : w4.w;
                    u64 wd = pack2(wv, wv);
                    u64 p0, p1, p2, p3;
                    unsigned ad = hbase + (q * 4 + cc) * 32;
                    lds_2x64(p0, p1, ad);
                    lds_2x64(p2, p3, ad + 16);
                    ffma2(a0, wd, p0); ffma2(a1, wd, p1);
                    ffma2(a2, wd, p2); ffma2(a3, wd, p3);
                }
            }
        }

        sts_2x64(pbase, a0, a1);
        sts_2x64(pbase + 16, a2, a3);
        __syncthreads();

        // ---- reduce + gates + state update + h-block store ----
        if (tid < 128) {
            const int j2 = tid >> 3, b = tid & 7;
            float v[4];
#pragma unroll
            for (int g = 0; g < 4; ++g) {
                int rr = g * 16 + j2;
                float s = bsh[rr];
#pragma unroll
                for (int k8 = 0; k8 < 8; ++k8) s += psh[k8 * 512 + rr * 8 + b];
                v[g] = s;
            }
            float ig = sigf(v[0]);
            float fg = sigf(v[1]);
            float gv = tanh_f(v[2]);
            float og = sigf(v[3]);
            c = fg * c + ig * gv;
            float h = og * tanh_f(c);
            __stcg(&d_H[((t & 1) * 8 + bt) * (HID * 8) + (ht * 16 + j2) * 8 + b], h);
        }
        __syncthreads();   // all h stores ordered before tid0's release

        if (tid == 0 && t < T_STEPS - 1)
            st_rel(&d_flag[(t * 8 + bt) * 16 + ht], 1u);
    }
}

// ============================================================================
// Kernel 3: logits = h @ lin_W.T + lin_b, grid (125, 2): batch halves
//   Software-pipelined: prefetch next k-row (16 u64) before current row's
//   16 FFMA2 -> LDS->use distance ~24 inst > 29-cyc LDS latency.
//   ~120 regs, 32KB smem -> 2 CTAs/SM. lin_W re-read hits L2 (33MB < 126MB).
// ============================================================================
__global__ void __launch_bounds__(256, 2)
out_kernel(const float* __restrict__ lin_W, const float* __restrict__ lin_b,
           float* __restrict__ out) {
    __shared__ __align__(16) float hsh[HID * 32 + 32];   // [k256][32b] + pad row
    const int tid  = threadIdx.x;
    const int half = blockIdx.y;

    // d_H buf0 [bt8][k256][8b] -> hsh [k][32 local b]
    for (int idx = tid; idx < HID * 32; idx += 256) {
        int k = idx >> 5, bl = idx & 31;
        int gb = half * 32 + bl;
        hsh[idx] = d_H[(gb >> 3) * (HID * 8) + k * 8 + (gb & 7)];
    }
    __syncthreads();

    const int v = blockIdx.x * 256 + tid;
    const unsigned hb = (unsigned)__cvta_generic_to_shared(hsh);

    float bbv = lin_b[v];
    u64 acc[16];
    u64 bp = pack2(bbv, bbv);
#pragma unroll
    for (int j = 0; j < 16; ++j) acc[j] = bp;

    u64 bufA[16], bufB[16];
    // preload k-row 0 into bufA (row = 128B contiguous, warp-broadcast)
#pragma unroll
    for (int j = 0; j < 8; ++j) lds_2x64(bufA[2 * j], bufA[2 * j + 1], hb + j * 16);

    const float4* wp = (const float4*)(lin_W + v * HID);
#pragma unroll 1
    for (int kk = 0; kk < HID / 4; ++kk) {
        float4 w4 = wp[kk];
#pragma unroll
        for (int cc = 0; cc < 4; ++cc) {
            const int kidx = 0 * 4 + cc;       // parity within the 4-group
            // prefetch row (kk*4+cc+1) into the other buffer (last reads pad)
            unsigned nbase = hb + (unsigned)(kk * 4 + cc + 1) * 128;
            if ((kidx & 1) == 0) {
#pragma unroll
                for (int j = 0; j < 8; ++j)
                    lds_2x64(bufB[2 * j], bufB[2 * j + 1], nbase + j * 16);
            } else {
#pragma unroll
                for (int j = 0; j < 8; ++j)
                    lds_2x64(bufA[2 * j], bufA[2 * j + 1], nbase + j * 16);
            }
            float wv = (cc == 0) ? w4.x : (cc == 1) ? w4.y : (cc == 2) ? w4.z : w4.w;
            u64 wd = pack2(wv, wv);
            if ((kidx & 1) == 0) {
#pragma unroll
                for (int j = 0; j < 16; ++j) ffma2(acc[j], wd, bufA[j]);
            } else {
#pragma unroll
                for (int j = 0; j < 16; ++j) ffma2(acc[j], wd, bufB[j]);
            }
        }
    }

#pragma unroll
    for (int j = 0; j < 16; ++j) {
        float x0, x1;
        unpack2(acc[j], x0, x1);
        int gb = half * 32 + 2 * j;
        out[gb * VOCAB + v]       = x0;
        out[(gb + 1) * VOCAB + v] = x1;
    }
}

// ============================================================================
// launch
// ============================================================================
extern "C" void kernel_launch(void* const* d_in, const int* in_sizes, int n_in,
                              void* d_out, int out_size) {
    const int*   story  = (const int*)d_in[0];
    const int*   query  = (const int*)d_in[1];
    const float* E      = (const float*)d_in[2];
    const float* W_ih   = (const float*)d_in[3];
    const float* W_hh   = (const float*)d_in[4];
    const float* b_ih   = (const float*)d_in[5];
    const float* b_hh   = (const float*)d_in[6];
    const float* lin_W  = (const float*)d_in[7];
    const float* lin_b  = (const float*)d_in[8];
    float*       out    = (float*)d_out;

    clear_flags_kernel<<<(NFLAGS + 255) / 256, 256>>>();
    encode_kernel<<<(T_STEPS * BSZ) / 8, 256>>>(story, query, E);
    lstm_kernel<<<RGRID, RTHREADS>>>(W_ih, W_hh, b_ih, b_hh);
    dim3 og(VOCAB / 256, 2);
    out_kernel<<<og, 256>>>(lin_W, lin_b, out);
}

// round 11
// speedup vs baseline: 1.4049x; 1.0111x over previous
#include <cuda_runtime.h>

// ---------------- problem constants ----------------
#define T_STEPS 131   // 128 story + 1 query + 2 empty
#define BSZ     64
#define EMB     128
#define HID     256
#define VOCAB   32000
#define MSTL    128
#define MSEL    24
#define QL      16

// ---------------- scratch ----------------
// d_X: [t(<=128)][bt8][e128][b8]  (per-CTA tile contiguous 4KB)
__device__ __align__(16) float d_X[129 * 8 * EMB * 8];
// d_H: h double buffer [buf2][bt8][k256][b8] (per-producer block = 512B)
__device__ __align__(16) float d_H[2 * 8 * HID * 8];
// one flag per (t, bt, producer ht); cleared before each run
#define NFLAGS (T_STEPS * 8 * 16)
__device__ unsigned d_flag[NFLAGS];

// ---------------- helpers ----------------
typedef unsigned long long u64;

__device__ __forceinline__ u64 pack2(float x, float y) {
    u64 r; asm("mov.b64 %0, {%1, %2};" : "=l"(r) : "f"(x), "f"(y)); return r;
}
__device__ __forceinline__ void ffma2(u64& acc, u64 a, u64 b) {
    asm("fma.rn.f32x2 %0, %1, %2, %0;" : "+l"(acc) : "l"(a), "l"(b));
}
__device__ __forceinline__ void lds_2x64(u64& p0, u64& p1, unsigned addr) {
    asm volatile("ld.shared.v2.u64 {%0, %1}, [%2];" : "=l"(p0), "=l"(p1) : "r"(addr));
}
__device__ __forceinline__ void sts_2x64(unsigned addr, u64 p0, u64 p1) {
    asm volatile("st.shared.v2.u64 [%0], {%1, %2};" :: "r"(addr), "l"(p0), "l"(p1));
}
__device__ __forceinline__ void unpack2(u64 p, float& x, float& y) {
    asm("mov.b64 {%0, %1}, %2;" : "=f"(x), "=f"(y) : "l"(p));
}
__device__ __forceinline__ void cp_async16(unsigned smem, const void* gptr) {
    asm volatile("cp.async.cg.shared.global [%0], [%1], 16;" :: "r"(smem), "l"(gptr));
}
__device__ __forceinline__ void cp_commit() { asm volatile("cp.async.commit_group;"); }
__device__ __forceinline__ void cp_wait0()  { asm volatile("cp.async.wait_group 0;"); }

__device__ __forceinline__ unsigned ld_acq(const unsigned* p) {
    unsigned v;
    asm volatile("ld.acquire.gpu.global.b32 %0, [%1];" : "=r"(v) : "l"(p));
    return v;
}
__device__ __forceinline__ void st_rel(unsigned* p, unsigned v) {
    asm volatile("st.release.gpu.global.b32 [%0], %1;" :: "l"(p), "r"(v));
}

__device__ __forceinline__ float sigf(float x) {
    return 1.0f / (1.0f + __expf(-x));
}
__device__ __forceinline__ float tanh_f(float x) {
    float a = fabsf(x);
    float e = __expf(-2.0f * a);
    float r = (1.0f - e) / (1.0f + e);
    return copysignf(r, x);
}

// ============================================================================
// Kernel 0: clear flags (graph replays must start from zero)
// ============================================================================
__global__ void clear_flags_kernel() {
    int i = blockIdx.x * 256 + threadIdx.x;
    if (i < NFLAGS) d_flag[i] = 0;
}

// ============================================================================
// Kernel 1: embedding gather + position encoding -> d_X [t][bt8][e][8b]
// ============================================================================
__global__ void encode_kernel(const int* __restrict__ story,
                              const int* __restrict__ query,
                              const float* __restrict__ E) {
    int wid  = blockIdx.x * 8 + (threadIdx.x >> 5);
    int lane = threadIdx.x & 31;
    int b = wid / T_STEPS;
    int t = wid % T_STEPS;
    if (t > MSTL) return;
    int e0 = lane * 4;

    const float invE = 1.0f / (float)EMB;
    float k0 = (e0 + 1) * invE;
    float k1 = (e0 + 2) * invE;
    float k2 = (e0 + 3) * invE;
    float k3 = (e0 + 4) * invE;

    float4 acc = make_float4(0.f, 0.f, 0.f, 0.f);

    if (t < MSTL) {
        const int* toks = story + (b * MSTL + t) * MSEL;
#pragma unroll
        for (int s = 0; s < MSEL; ++s) {
            int tok = toks[s];
            float j = (s + 1) * (1.0f / 32.0f);
            float A = 1.0f - j, Bc = 1.0f - 2.0f * j;
            float4 ev = *(const float4*)(E + tok * EMB + e0);
            acc.x += ev.x * (A - k0 * Bc);
            acc.y += ev.y * (A - k1 * Bc);
            acc.z += ev.z * (A - k2 * Bc);
            acc.w += ev.w * (A - k3 * Bc);
        }
    } else {
        const int* toks = query + b * QL;
#pragma unroll
        for (int s = 0; s < QL; ++s) {
            int tok = toks[s];
            float j = (s + 1) * (1.0f / 32.0f);
            float A = 1.0f - j, Bc = 1.0f - 2.0f * j;
            float4 ev = *(const float4*)(E + tok * EMB + e0);
            acc.x += ev.x * (A - k0 * Bc);
            acc.y += ev.y * (A - k1 * Bc);
            acc.z += ev.z * (A - k2 * Bc);
            acc.w += ev.w * (A - k3 * Bc);
        }
    }
    float* dst = d_X + ((t * 8 + (b >> 3)) * EMB) * 8 + (b & 7);
    dst[(e0 + 0) * 8] = acc.x;
    dst[(e0 + 1) * 8] = acc.y;
    dst[(e0 + 2) * 8] = acc.z;
    dst[(e0 + 3) * 8] = acc.w;
}

// ============================================================================
// Kernel 2: persistent LSTM recurrence, flag-based L2 exchange (R6 design
//   + own-block STS shortcut).
//   128 CTAs = 16 ht x 8 bt, 512 threads: kc=tid>>6 (k-chunk 0..7), r=tid&63.
// ============================================================================
#define RGRID 128
#define RTHREADS 512

__global__ void __launch_bounds__(RTHREADS, 1)
lstm_kernel(const float* __restrict__ W_ih, const float* __restrict__ W_hh,
            const float* __restrict__ b_ih, const float* __restrict__ b_hh) {
    __shared__ __align__(16) float xsh[2][EMB * 8];   // 2 x 4KB, [e][8b]
    __shared__ __align__(16) float hsh[HID * 8];      // 8KB, [k][8b]
    __shared__ __align__(16) float psh[512 * 8];      // 16KB partials
    __shared__ float bsh[64];

    const int tid = threadIdx.x;
    const int bt  = blockIdx.x & 7;
    const int ht  = blockIdx.x >> 3;
    const int kc  = tid >> 6;          // 0..7
    const int r   = tid & 63;          // g*16 + jj
    const int grow = (r >> 4) * 256 + ht * 16 + (r & 15);

    // ---- register-resident weight slices ----
    float4 wih[4];    // W_ih[grow][kc*16 .. +16)
    float4 whh[8];    // W_hh[grow][kc*32 .. +32)
    {
        const float4* p = (const float4*)(W_ih + grow * EMB + kc * 16);
#pragma unroll
        for (int q = 0; q < 4; ++q) wih[q] = p[q];
        const float4* ph = (const float4*)(W_hh + grow * HID + kc * 32);
#pragma unroll
        for (int q = 0; q < 8; ++q) whh[q] = ph[q];
    }
    if (tid < 64) {
        int gr = (tid >> 4) * 256 + ht * 16 + (tid & 15);
        bsh[tid] = b_ih[gr] + b_hh[gr];
    }

    const unsigned xs0  = (unsigned)__cvta_generic_to_shared(&xsh[0][0]);
    const unsigned hsb  = (unsigned)__cvta_generic_to_shared(hsh);
    const unsigned hbase = hsb + kc * 1024;
    const unsigned pbase = (unsigned)__cvta_generic_to_shared(psh) + tid * 32;

    const int w    = tid >> 5;   // warp id 0..15 (one producer each)
    const int lane = tid & 31;

    // prefetch x(0)
    if (tid < 256) cp_async16(xs0 + tid * 16, d_X + bt * (EMB * 8) + tid * 4);
    cp_commit();

    float c = 0.0f;
    __syncthreads();   // bsh ready

    for (int t = 0; t < T_STEPS; ++t) {
        u64 a0 = 0, a1 = 0, a2 = 0, a3 = 0;

        if (t <= MSTL) {
            cp_wait0();
            __syncthreads();                        // x(t) visible CTA-wide
            if (t < MSTL) {
                if (tid < 256)
                    cp_async16(xs0 + (((t + 1) & 1) ? 4096 : 0) + tid * 16,
                               d_X + (((t + 1) * 8 + bt) * EMB) * 8 + tid * 4);
                cp_commit();
            }
            // ---- x-part GEMM (latency filler before the flag wait) ----
            const unsigned xb = xs0 + ((t & 1) ? 4096 : 0) + kc * 512;
#pragma unroll
            for (int q = 0; q < 4; ++q) {
                float4 w4 = wih[q];
#pragma unroll
                for (int cc = 0; cc < 4; ++cc) {
                    float wv = (cc == 0) ? w4.x : (cc == 1) ? w4.y : (cc == 2) ? w4.z : w4.w;
                    u64 wd = pack2(wv, wv);
                    u64 p0, p1, p2, p3;
                    unsigned ad = xb + (q * 4 + cc) * 32;
                    lds_2x64(p0, p1, ad);
                    lds_2x64(p2, p3, ad + 16);
                    ffma2(a0, wd, p0); ffma2(a1, wd, p1);
                    ffma2(a2, wd, p2); ffma2(a3, wd, p3);
                }
            }
        }

        if (t > 0) {
            // ---- fine-grained exchange: warp w waits on producer w, then
            //      streams its 512B h-block. Own block (w==ht) was written
            //      directly into hsh at publish time -> skip poll+cp. ----
            if (w != ht) {
                const unsigned* fp = &d_flag[((t - 1) * 8 + bt) * 16 + w];
                while (ld_acq(fp) == 0) { }
                const float* src = d_H + (((t - 1) & 1) * 8 + bt) * (HID * 8)
                                   + w * 128 + lane * 4;
                cp_async16(hsb + w * 512 + lane * 16, src);
            }
            cp_commit();
            cp_wait0();
            __syncthreads();                        // whole h(t-1) tile visible

            // ---- h-part GEMM ----
#pragma unroll
            for (int q = 0; q < 8; ++q) {
                float4 w4 = whh[q];
#pragma unroll
                for (int cc = 0; cc < 4; ++cc) {
                    float wv = (cc == 0) ? w4.x : (cc == 1) ? w4.y : (cc == 2) ? w4.z : w4.w;
                    u64 wd = pack2(wv, wv);
                    u64 p0, p1, p2, p3;
                    unsigned ad = hbase + (q * 4 + cc) * 32;
                    lds_2x64(p0, p1, ad);
                    lds_2x64(p2, p3, ad + 16);
                    ffma2(a0, wd, p0); ffma2(a1, wd, p1);
                    ffma2(a2, wd, p2); ffma2(a3, wd, p3);
                }
            }
        }

        sts_2x64(pbase, a0, a1);
        sts_2x64(pbase + 16, a2, a3);
        __syncthreads();

        // ---- reduce + gates + state update + h publish ----
        if (tid < 128) {
            const int j2 = tid >> 3, b = tid & 7;
            float v[4];
#pragma unroll
            for (int g = 0; g < 4; ++g) {
                int rr = g * 16 + j2;
                float s = bsh[rr];
#pragma unroll
                for (int k8 = 0; k8 < 8; ++k8) s += psh[k8 * 512 + rr * 8 + b];
                v[g] = s;
            }
            float ig = sigf(v[0]);
            float fg = sigf(v[1]);
            float gv = tanh_f(v[2]);
            float og = sigf(v[3]);
            c = fg * c + ig * gv;
            float h = og * tanh_f(c);
            // local own-block publish (read next step by this CTA itself)
            hsh[ht * 128 + j2 * 8 + b] = h;
            // global publish for peer CTAs
            __stcg(&d_H[((t & 1) * 8 + bt) * (HID * 8) + (ht * 16 + j2) * 8 + b], h);
        }
        __syncthreads();   // all h stores ordered before tid0's release

        if (tid == 0 && t < T_STEPS - 1)
            st_rel(&d_flag[(t * 8 + bt) * 16 + ht], 1u);
    }
}

// ============================================================================
// Kernel 3: logits = h @ lin_W.T + lin_b  ([64,256] x [256,32000])
//   125 CTAs x 256 threads; 1 vocab col/thread, 64 batches (32 u64 accs).
//   lin_W prefetched 8 float4 deep -> MLP 8/thread hides DRAM latency.
// ============================================================================
__global__ void __launch_bounds__(256, 1)
out_kernel(const float* __restrict__ lin_W, const float* __restrict__ lin_b,
           float* __restrict__ out) {
    extern __shared__ float hsh[];  // [256 k][64 b], 64 KB
    const int tid = threadIdx.x;
    {
        // d_H buf0 [bt8][k256][8b] -> hsh [k][64b]
        const float4* src = (const float4*)d_H;
        for (int idx4 = tid; idx4 < 4096; idx4 += 256) {
            int btx = idx4 >> 9, k = (idx4 >> 1) & 255, half = idx4 & 1;
            float4 v = src[idx4];
            *(float4*)(hsh + k * 64 + btx * 8 + half * 4) = v;
        }
    }
    __syncthreads();

    const int v = blockIdx.x * 256 + tid;
    const unsigned hb = (unsigned)__cvta_generic_to_shared(hsh);

    float bbv = lin_b[v];
    u64 acc[32];
    u64 bp = pack2(bbv, bbv);
#pragma unroll
    for (int j = 0; j < 32; ++j) acc[j] = bp;

    const float4* wp = (const float4*)(lin_W + v * HID);

#pragma unroll 1
    for (int g8 = 0; g8 < 8; ++g8) {
        // ---- 8-deep weight prefetch: 8 independent LDG.128 in flight ----
        float4 w4[8];
#pragma unroll
        for (int j = 0; j < 8; ++j) w4[j] = wp[g8 * 8 + j];

#pragma unroll
        for (int j = 0; j < 8; ++j) {
#pragma unroll
            for (int cc = 0; cc < 4; ++cc) {
                float wv = (cc == 0) ? w4[j].x : (cc == 1) ? w4[j].y
                         : (cc == 2) ? w4[j].z : w4[j].w;
                u64 wd = pack2(wv, wv);
                unsigned base = hb + (((g8 * 8 + j) * 4 + cc) * BSZ) * 4;
#pragma unroll
                for (int p = 0; p < 8; ++p) {
                    u64 q0, q1, q2, q3;
                    lds_2x64(q0, q1, base + p * 32);
                    lds_2x64(q2, q3, base + p * 32 + 16);
                    ffma2(acc[p * 4 + 0], wd, q0);
                    ffma2(acc[p * 4 + 1], wd, q1);
                    ffma2(acc[p * 4 + 2], wd, q2);
                    ffma2(acc[p * 4 + 3], wd, q3);
                }
            }
        }
    }

#pragma unroll
    for (int j = 0; j < 32; ++j) {
        float f0, f1;
        unpack2(acc[j], f0, f1);
        out[(2 * j) * VOCAB + v]     = f0;
        out[(2 * j + 1) * VOCAB + v] = f1;
    }
}

// ============================================================================
// launch
// ============================================================================
extern "C" void kernel_launch(void* const* d_in, const int* in_sizes, int n_in,
                              void* d_out, int out_size) {
    const int*   story  = (const int*)d_in[0];
    const int*   query  = (const int*)d_in[1];
    const float* E      = (const float*)d_in[2];
    const float* W_ih   = (const float*)d_in[3];
    const float* W_hh   = (const float*)d_in[4];
    const float* b_ih   = (const float*)d_in[5];
    const float* b_hh   = (const float*)d_in[6];
    const float* lin_W  = (const float*)d_in[7];
    const float* lin_b  = (const float*)d_in[8];
    float*       out    = (float*)d_out;

    cudaFuncSetAttribute(out_kernel, cudaFuncAttributeMaxDynamicSharedMemorySize,
                         HID * BSZ * 4);

    clear_flags_kernel<<<(NFLAGS + 255) / 256, 256>>>();
    encode_kernel<<<(T_STEPS * BSZ) / 8, 256>>>(story, query, E);
    lstm_kernel<<<RGRID, RTHREADS>>>(W_ih, W_hh, b_ih, b_hh);
    out_kernel<<<VOCAB / 256, 256, HID * BSZ * 4>>>(lin_W, lin_b, out);
}